// round 2
// baseline (speedup 1.0000x reference)
#include <cuda_runtime.h>
#include <math.h>
#include <stdint.h>

#define NCUT 200000
#define GOI  500
#define BB   512
#define LL   16
#define CC   224
#define GTOT 20000
#define LOG2PI 1.8378770664093453

// ---------------- device scratch ----------------
__device__ float  g_lw[GOI * LL * CC];   // gathered logit weights
__device__ float4 g_spl[GOI * CC];       // per-gene spline params {uh, ww, loc, w}
__device__ float  g_z[BB * GTOT];        // unnormalized log-rho
__device__ float  g_logZ[BB];
__device__ int    g_off[GOI + 1];
__device__ int    g_woff[GOI];
__device__ int4   g_cut[NCUT];           // {x_bits, gl, b, li} sorted by g2
__device__ double g_acc[2];

// ---------------- helpers ----------------
__device__ __forceinline__ unsigned long long pk(float a, float b) {
    unsigned long long r;
    asm("mov.b64 %0, {%1,%2};" : "=l"(r) : "f"(a), "f"(b));
    return r;
}
__device__ __forceinline__ void upk(unsigned long long p, float& a, float& b) {
    asm("mov.b64 {%0,%1}, %2;" : "=f"(a), "=f"(b) : "l"(p));
}
__device__ __forceinline__ void fma2(unsigned long long& d, unsigned long long a, unsigned long long b) {
    asm("fma.rn.f32x2 %0, %1, %2, %0;" : "+l"(d) : "l"(a), "l"(b));
}
__device__ __forceinline__ int redux_add(int v) {
    int r;
    asm("redux.sync.add.s32 %0, %1, 0xffffffff;" : "=r"(r) : "r"(v));
    return r;
}
__device__ __forceinline__ float sel4(float a, float b, float c, float d, int j) {
    float lo = (j & 1) ? b : a;
    float hi = (j & 1) ? d : c;
    return (j & 2) ? hi : lo;
}
__device__ __forceinline__ float sel2(float a, float b, int j) { return j ? b : a; }
__device__ __forceinline__ int iminmax(int v, int hi) { v = v < 0 ? 0 : v; return v > hi ? hi : v; }

// ---------------- K0: init ----------------
__global__ void k_init() {
    int t = threadIdx.x;
    if (t < 2) g_acc[t] = 0.0;
    for (int i = t; i <= GOI; i += blockDim.x) g_off[i] = 0;
}

// ---------------- K1: per-gene precompute ----------------
__global__ void k_pergene(const int* __restrict__ genes_oi,
                          const float* __restrict__ logit_weight,
                          const float* __restrict__ rho_weight,
                          const float* __restrict__ uh,
                          const float* __restrict__ uw) {
    int g = blockIdx.x, t = threadIdx.x;
    int gene = genes_oi[g];

    float psum = 0.f;
    const float* lwr = logit_weight + (size_t)gene * (LL * CC);
    for (int i = t; i < LL * CC; i += blockDim.x) {
        float v = lwr[i];
        g_lw[g * (LL * CC) + i] = v;
        psum -= 0.5f * v * v;
    }
    if (t < LL) { float v = rho_weight[gene * LL + t]; psum -= 0.5f * v * v; }

    __shared__ float s_red[128];
    __shared__ float s_w[128];
    __shared__ float s_scan[128];

    const int nh_t[3] = {128, 64, 32};
    const int oh_t[3] = {0, 128, 192};
    const int ow_t[3] = {0, 127, 190};
    const float* uhr = uh + (size_t)gene * CC;
    const float* uwr = uw + (size_t)gene * 221;

    for (int s = 0; s < 3; s++) {
        int nh = nh_t[s], nw = nh - 1, oh = oh_t[s], ow = ow_t[s];
        float uwv = (t < nw) ? uwr[ow + t] : -1e30f;
        s_red[t] = uwv; __syncthreads();
        for (int o = 64; o; o >>= 1) { if (t < o) s_red[t] = fmaxf(s_red[t], s_red[t + o]); __syncthreads(); }
        float mx = s_red[0]; __syncthreads();
        float e = (t < nw) ? __expf(uwv - mx) : 0.f;
        s_red[t] = e; __syncthreads();
        for (int o = 64; o; o >>= 1) { if (t < o) s_red[t] += s_red[t + o]; __syncthreads(); }
        float inv = 1.0f / s_red[0]; __syncthreads();
        float w = e * inv;
        s_w[t] = w;
        s_scan[t] = w;
        __syncthreads();
        for (int o = 1; o < 128; o <<= 1) {
            float v = (t >= o) ? s_scan[t - o] : 0.f;
            __syncthreads();
            s_scan[t] += v;
            __syncthreads();
        }
        if (t < nh) {
            float loc = (t == 0) ? 0.f : ((t == nw) ? 1.0f : s_scan[t - 1]);
            float wl = (t >= 1) ? s_w[t - 1] : 0.f;
            float wr = (t <= nw - 1) ? w : 0.f;
            float wwv = 0.5f * (wl + wr);
            float wst = (t < nw) ? w : 0.f;
            g_spl[g * CC + oh + t] = make_float4(uhr[oh + t], wwv, loc, wst);
        }
        __syncthreads();
    }

    s_red[t] = psum; __syncthreads();
    for (int o = 64; o; o >>= 1) { if (t < o) s_red[t] += s_red[t + o]; __syncthreads(); }
    if (t == 0) atomicAdd(&g_acc[1], (double)s_red[0]);
}

// ---------------- counting sort by g2 ----------------
__global__ void k_hist(const int* __restrict__ lci, int n, int G) {
    int i = blockIdx.x * blockDim.x + threadIdx.x;
    if (i < n) atomicAdd(&g_off[lci[i] % G], 1);
}

__global__ void k_scan(int G) {
    int t = threadIdx.x, lane = t & 31, w = t >> 5;
    int v = (t < G) ? g_off[t] : 0;
    int s = v;
#pragma unroll
    for (int o = 1; o < 32; o <<= 1) {
        int u = __shfl_up_sync(0xffffffffu, s, o);
        if (lane >= o) s += u;
    }
    __shared__ int ws[16];
    if (lane == 31) ws[w] = s;
    __syncthreads();
    if (w == 0) {
        int x = (lane < 16) ? ws[lane] : 0;
#pragma unroll
        for (int o = 1; o < 16; o <<= 1) {
            int u = __shfl_up_sync(0xffffffffu, x, o);
            if (lane >= o) x += u;
        }
        if (lane < 16) ws[lane] = x;
    }
    __syncthreads();
    int base = (w > 0) ? ws[w - 1] : 0;
    int excl = s + base - v;
    if (t <= G) g_off[t] = excl;
    if (t < G)  g_woff[t] = excl;
}

__global__ void k_scatter(const int* __restrict__ lci,
                          const int* __restrict__ lgi,
                          const int* __restrict__ lcgi,
                          const float* __restrict__ coord,
                          int n, int G) {
    int i = blockIdx.x * blockDim.x + threadIdx.x;
    if (i < n) {
        int ci = lci[i];
        int g = ci % G;
        int b = ci / G;
        int p = atomicAdd(&g_woff[g], 1);
        g_cut[p] = make_int4(__float_as_int(coord[i]), lgi[i], b, lcgi[i]);
    }
}

// ---------------- K2a: z ----------------
__global__ void k_z(const float* __restrict__ clustering,
                    const float* __restrict__ rho_weight,
                    const float* __restrict__ rho_bias, int GT) {
    int j = blockIdx.x * blockDim.x + threadIdx.x;
    if (j >= GT) return;
    int b0 = blockIdx.y * 8;
    float lb = __logf(rho_bias[j]);
    const float4* rw = (const float4*)(rho_weight + (size_t)j * LL);
    float4 r0 = rw[0], r1 = rw[1], r2 = rw[2], r3 = rw[3];
#pragma unroll
    for (int bi = 0; bi < 8; bi++) {
        int b = b0 + bi;
        const float4* cp = (const float4*)(clustering + (size_t)b * LL);
        float4 c0 = cp[0], c1 = cp[1], c2 = cp[2], c3 = cp[3];
        float z = lb;
        z = fmaf(c0.x, r0.x, z); z = fmaf(c0.y, r0.y, z); z = fmaf(c0.z, r0.z, z); z = fmaf(c0.w, r0.w, z);
        z = fmaf(c1.x, r1.x, z); z = fmaf(c1.y, r1.y, z); z = fmaf(c1.z, r1.z, z); z = fmaf(c1.w, r1.w, z);
        z = fmaf(c2.x, r2.x, z); z = fmaf(c2.y, r2.y, z); z = fmaf(c2.z, r2.z, z); z = fmaf(c2.w, r2.w, z);
        z = fmaf(c3.x, r3.x, z); z = fmaf(c3.y, r3.y, z); z = fmaf(c3.z, r3.z, z); z = fmaf(c3.w, r3.w, z);
        g_z[(size_t)b * GT + j] = z;
    }
}

// ---------------- K2b: logsumexp ----------------
__global__ void k_lse(int GT) {
    int b = blockIdx.x, t = threadIdx.x;
    const float* zr = g_z + (size_t)b * GT;
    float m = -1e30f, s = 0.f;
    for (int j = t; j < GT; j += blockDim.x) {
        float v = zr[j];
        if (v > m) { s = s * __expf(m - v) + 1.f; m = v; }
        else       { s += __expf(v - m); }
    }
    __shared__ float sm[256], ss[256];
    sm[t] = m; ss[t] = s; __syncthreads();
    for (int o = 128; o; o >>= 1) {
        if (t < o) {
            float m1 = sm[t], s1 = ss[t], m2 = sm[t + o], s2 = ss[t + o];
            float M = fmaxf(m1, m2);
            sm[t] = M;
            ss[t] = s1 * __expf(m1 - M) + s2 * __expf(m2 - M);
        }
        __syncthreads();
    }
    if (t == 0) g_logZ[b] = sm[0] + logf(ss[0]);
}

// ---------------- K3: main per-cut kernel ----------------
__global__ void __launch_bounds__(256, 1) k_main(const float* __restrict__ clustering,
                                                 int GT, float logGT) {
    __shared__ __align__(16) float s_lw[LL * CC];
    __shared__ double s_acc[8];
    int g = blockIdx.x, t = threadIdx.x;
    int wid = t >> 5, lane = t & 31;

    for (int i = t; i < LL * CC; i += 256) s_lw[i] = g_lw[g * (LL * CC) + i];
    __syncthreads();

    // register-resident lw tile (cut-invariant per lane)
    unsigned long long lw1[32];   // step1: cols lane*4 + {0..3}, packed pairs, per l
    unsigned long long lw2[16];   // step2: cols 128 + lane*2 + {0,1}
    float lw3[16];                // step3: col 192 + lane
#pragma unroll
    for (int l = 0; l < 16; l++) {
        float4 v = *(const float4*)&s_lw[l * CC + (lane << 2)];
        lw1[2 * l]     = pk(v.x, v.y);
        lw1[2 * l + 1] = pk(v.z, v.w);
        float2 u = *(const float2*)&s_lw[l * CC + 128 + (lane << 1)];
        lw2[l] = pk(u.x, u.y);
        lw3[l] = s_lw[l * CC + 192 + lane];
    }

    int start = g_off[g], end = g_off[g + 1];
    double acc = 0.0;

    for (int k = start + wid; k < end; k += 8) {
        int4 cd = g_cut[k];
        float x = __int_as_float(cd.x);
        int gl = cd.y, b = cd.z, li = cd.w;

        // issue all spline-param loads up front (MLP)
        const float4* splg = g_spl + (size_t)gl * CC;
        float4 p0 = __ldg(splg + (lane << 2) + 0);
        float4 p1 = __ldg(splg + (lane << 2) + 1);
        float4 p2 = __ldg(splg + (lane << 2) + 2);
        float4 p3 = __ldg(splg + (lane << 2) + 3);
        float4 q0 = __ldg(splg + 128 + (lane << 1) + 0);
        float4 q1 = __ldg(splg + 128 + (lane << 1) + 1);
        float4 r0 = __ldg(splg + 192 + lane);
        float zc = __ldg(&g_z[li]);
        float lZ = __ldg(&g_logZ[li / GT]);

        const float4* cp = (const float4*)(clustering + (size_t)b * LL);
        float4 c0 = cp[0], c1 = cp[1], c2 = cp[2], c3 = cp[3];
        float cl[16] = {c0.x, c0.y, c0.z, c0.w, c1.x, c1.y, c1.z, c1.w,
                        c2.x, c2.y, c2.z, c2.w, c3.x, c3.y, c3.z, c3.w};

        float lad = 0.f;

        // ================= step 1 (128 heights, K=4) =================
        {
            unsigned long long d01 = 0ull, d23 = 0ull;
#pragma unroll
            for (int l = 0; l < 16; l++) {
                unsigned long long c2p = pk(cl[l], cl[l]);
                fma2(d01, c2p, lw1[2 * l]);
                fma2(d23, c2p, lw1[2 * l + 1]);
            }
            float d0, d1, d2, d3;
            upk(d01, d0, d1); upk(d23, d2, d3);
            float h0 = __expf(p0.x + d0), h1 = __expf(p1.x + d1);
            float h2 = __expf(p2.x + d2), h3 = __expf(p3.x + d3);

            int cnt = (x >= p0.z) + (x >= p1.z) + (x >= p2.z) + (x >= p3.z);
            cnt = redux_add(cnt);
            int bin = iminmax(cnt - 1, 126);

            float wprev = __shfl_up_sync(0xffffffffu, p3.w, 1);
            int i0 = lane << 2;
            float area = h0 * p0.y;
            area = fmaf(h1, p1.y, area); area = fmaf(h2, p2.y, area); area = fmaf(h3, p3.y, area);
            float ct0 = ((i0 < bin) ? 0.5f * p0.w : 0.f) + ((i0 >= 1 && i0 <= bin) ? 0.5f * wprev : 0.f);
            float ct1 = ((i0 + 1 < bin) ? 0.5f * p1.w : 0.f) + ((i0 + 1 <= bin) ? 0.5f * p0.w : 0.f);
            float ct2 = ((i0 + 2 < bin) ? 0.5f * p2.w : 0.f) + ((i0 + 2 <= bin) ? 0.5f * p1.w : 0.f);
            float ct3 = ((i0 + 3 < bin) ? 0.5f * p3.w : 0.f) + ((i0 + 3 <= bin) ? 0.5f * p2.w : 0.f);
            float cdf = h0 * ct0;
            cdf = fmaf(h1, ct1, cdf); cdf = fmaf(h2, ct2, cdf); cdf = fmaf(h3, ct3, cdf);
#pragma unroll
            for (int o = 16; o; o >>= 1) {
                area += __shfl_xor_sync(0xffffffffu, area, o);
                cdf  += __shfl_xor_sync(0xffffffffu, cdf, o);
            }
            int jb = bin & 3, lb = bin >> 2;
            int jb1 = (bin + 1) & 3, lb1 = (bin + 1) >> 2;
            float hl   = __shfl_sync(0xffffffffu, sel4(h0, h1, h2, h3, jb),  lb);
            float hr   = __shfl_sync(0xffffffffu, sel4(h0, h1, h2, h3, jb1), lb1);
            float locl = __shfl_sync(0xffffffffu, sel4(p0.z, p1.z, p2.z, p3.z, jb), lb);
            float wb   = __shfl_sync(0xffffffffu, sel4(p0.w, p1.w, p2.w, p3.w, jb), lb);
            float inv = __fdividef(1.f, area);
            float alpha = __fdividef(x - locl, wb);
            float hln = hl * inv, hrn = hr * inv;
            x = (0.5f * (hrn - hln) * alpha + hln) * wb * alpha + cdf * inv;
            lad += __logf(fmaf(hrn - hln, alpha, hln));
        }

        // ================= step 2 (64 heights, K=2) =================
        {
            unsigned long long d01 = 0ull;
#pragma unroll
            for (int l = 0; l < 16; l++) {
                unsigned long long c2p = pk(cl[l], cl[l]);
                fma2(d01, c2p, lw2[l]);
            }
            float d0, d1;
            upk(d01, d0, d1);
            float h0 = __expf(q0.x + d0), h1 = __expf(q1.x + d1);

            int cnt = (x >= q0.z) + (x >= q1.z);
            cnt = redux_add(cnt);
            int bin = iminmax(cnt - 1, 62);

            float wprev = __shfl_up_sync(0xffffffffu, q1.w, 1);
            int i0 = lane << 1;
            float area = fmaf(h1, q1.y, h0 * q0.y);
            float ct0 = ((i0 < bin) ? 0.5f * q0.w : 0.f) + ((i0 >= 1 && i0 <= bin) ? 0.5f * wprev : 0.f);
            float ct1 = ((i0 + 1 < bin) ? 0.5f * q1.w : 0.f) + ((i0 + 1 <= bin) ? 0.5f * q0.w : 0.f);
            float cdf = fmaf(h1, ct1, h0 * ct0);
#pragma unroll
            for (int o = 16; o; o >>= 1) {
                area += __shfl_xor_sync(0xffffffffu, area, o);
                cdf  += __shfl_xor_sync(0xffffffffu, cdf, o);
            }
            int jb = bin & 1, lb = bin >> 1;
            int jb1 = (bin + 1) & 1, lb1 = (bin + 1) >> 1;
            float hl   = __shfl_sync(0xffffffffu, sel2(h0, h1, jb),  lb);
            float hr   = __shfl_sync(0xffffffffu, sel2(h0, h1, jb1), lb1);
            float locl = __shfl_sync(0xffffffffu, sel2(q0.z, q1.z, jb), lb);
            float wb   = __shfl_sync(0xffffffffu, sel2(q0.w, q1.w, jb), lb);
            float inv = __fdividef(1.f, area);
            float alpha = __fdividef(x - locl, wb);
            float hln = hl * inv, hrn = hr * inv;
            x = (0.5f * (hrn - hln) * alpha + hln) * wb * alpha + cdf * inv;
            lad += __logf(fmaf(hrn - hln, alpha, hln));
        }

        // ================= step 3 (32 heights, K=1) =================
        {
            float d = 0.f;
#pragma unroll
            for (int l = 0; l < 16; l++) d = fmaf(cl[l], lw3[l], d);
            float h0 = __expf(r0.x + d);

            int cnt = (x >= r0.z) ? 1 : 0;
            cnt = redux_add(cnt);
            int bin = iminmax(cnt - 1, 30);

            float wprev = __shfl_up_sync(0xffffffffu, r0.w, 1);
            float area = h0 * r0.y;
            float ct0 = ((lane < bin) ? 0.5f * r0.w : 0.f) + ((lane >= 1 && lane <= bin) ? 0.5f * wprev : 0.f);
            float cdf = h0 * ct0;
#pragma unroll
            for (int o = 16; o; o >>= 1) {
                area += __shfl_xor_sync(0xffffffffu, area, o);
                cdf  += __shfl_xor_sync(0xffffffffu, cdf, o);
            }
            float hl   = __shfl_sync(0xffffffffu, h0, bin);
            float hr   = __shfl_sync(0xffffffffu, h0, bin + 1);
            float locl = __shfl_sync(0xffffffffu, r0.z, bin);
            float wb   = __shfl_sync(0xffffffffu, r0.w, bin);
            float inv = __fdividef(1.f, area);
            float alpha = __fdividef(x - locl, wb);
            float hln = hl * inv, hrn = hr * inv;
            x = (0.5f * (hrn - hln) * alpha + hln) * wb * alpha + cdf * inv;
            lad += __logf(fmaf(hrn - hln, alpha, hln));
        }

        float lov = zc - lZ + logGT;
        if (lane == 0) acc += (double)(lad + lov);
    }

    if (lane == 0) s_acc[wid] = acc;
    __syncthreads();
    if (t == 0) {
        double tot = 0.0;
        for (int i = 0; i < 8; i++) tot += s_acc[i];
        atomicAdd(&g_acc[0], tot);
    }
}

// ---------------- K4: finalize ----------------
__global__ void k_final(float* out, int G) {
    double cnt = (double)G * (double)(LL * CC + LL);
    out[0] = (float)(-g_acc[0] - g_acc[1] + 0.5 * LOG2PI * cnt);
}

// ---------------- launch ----------------
extern "C" void kernel_launch(void* const* d_in, const int* in_sizes, int n_in,
                              void* d_out, int out_size) {
    const float* clustering    = (const float*)d_in[0];
    const float* coordinates   = (const float*)d_in[1];
    const int*   genes_oi      = (const int*)d_in[2];
    const int*   local_gene_ix = (const int*)d_in[3];
    const int*   lci           = (const int*)d_in[4];
    const int*   lcgi          = (const int*)d_in[5];
    const float* logit_weight  = (const float*)d_in[6];
    const float* rho_weight    = (const float*)d_in[7];
    const float* rho_bias      = (const float*)d_in[8];
    const float* uh            = (const float*)d_in[9];
    const float* uw            = (const float*)d_in[10];

    int N  = in_sizes[1];
    int G  = in_sizes[2];
    int B  = in_sizes[0] / LL;
    int GT = in_sizes[8];

    k_init<<<1, 512>>>();
    k_pergene<<<G, 128>>>(genes_oi, logit_weight, rho_weight, uh, uw);
    k_hist<<<(N + 255) / 256, 256>>>(lci, N, G);
    k_scan<<<1, 512>>>(G);
    k_scatter<<<(N + 255) / 256, 256>>>(lci, local_gene_ix, lcgi, coordinates, N, G);
    k_z<<<dim3((GT + 255) / 256, B / 8), 256>>>(clustering, rho_weight, rho_bias, GT);
    k_lse<<<B, 256>>>(GT);
    k_main<<<G, 256>>>(clustering, GT, logf((float)GT));
    k_final<<<1, 1>>>((float*)d_out, G);
}

// round 3
// speedup vs baseline: 1.1446x; 1.1446x over previous
#include <cuda_runtime.h>
#include <math.h>
#include <stdint.h>

#define NCUT 200000
#define GOI  500
#define BB   512
#define LL   16
#define CC   224
#define GTOT 20000
#define LOG2PI 1.8378770664093453

// ---------------- device scratch (zero-initialized at load; k_final restores) --
__device__ float  g_lw[GOI * LL * CC];
__device__ float4 g_spl[GOI * CC];       // {uh, ww, loc, w}
__device__ float  g_z[BB * GTOT];
__device__ float  g_logZ[BB];
__device__ int    g_off[GOI + 1];        // must be zero at entry of each replay
__device__ int    g_woff[GOI];
__device__ int4   g_cut[NCUT];           // {x_bits, gl, b, li}
__device__ double g_acc[2];              // [0]=lik (lad+rho), [1]=prior ; zero at entry

// ---------------- helpers ----------------
__device__ __forceinline__ int redux_add(int v) {
    int r;
    asm("redux.sync.add.s32 %0, %1, 0xffffffff;" : "=r"(r) : "r"(v));
    return r;
}
__device__ __forceinline__ float sel4(float a, float b, float c, float d, int j) {
    float lo = (j & 1) ? b : a;
    float hi = (j & 1) ? d : c;
    return (j & 2) ? hi : lo;
}
__device__ __forceinline__ float sel2(float a, float b, int j) { return j ? b : a; }
__device__ __forceinline__ int iminmax(int v, int hi) { v = v < 0 ? 0 : v; return v > hi ? hi : v; }

// ---------------- K1: fused per-gene precompute + histogram ----------------
__global__ void k_pergene_hist(const int* __restrict__ genes_oi,
                               const float* __restrict__ logit_weight,
                               const float* __restrict__ rho_weight,
                               const float* __restrict__ uh,
                               const float* __restrict__ uw,
                               const int* __restrict__ lci,
                               int n, int G) {
    int bid = blockIdx.x, t = threadIdx.x;
    if (bid >= G) {
        // histogram part
        int i = (bid - G) * 128 + t;
        if (i < n) atomicAdd(&g_off[lci[i] % G], 1);
        return;
    }
    int g = bid;
    int gene = genes_oi[g];

    float psum = 0.f;
    const float* lwr = logit_weight + (size_t)gene * (LL * CC);
    for (int i = t; i < LL * CC; i += 128) {
        float v = lwr[i];
        g_lw[g * (LL * CC) + i] = v;
        psum -= 0.5f * v * v;
    }
    if (t < LL) { float v = rho_weight[gene * LL + t]; psum -= 0.5f * v * v; }

    __shared__ float s_red[128];
    __shared__ float s_w[128];
    __shared__ float s_scan[128];

    const int nh_t[3] = {128, 64, 32};
    const int oh_t[3] = {0, 128, 192};
    const int ow_t[3] = {0, 127, 190};
    const float* uhr = uh + (size_t)gene * CC;
    const float* uwr = uw + (size_t)gene * 221;

    for (int s = 0; s < 3; s++) {
        int nh = nh_t[s], nw = nh - 1, oh = oh_t[s], ow = ow_t[s];
        float uwv = (t < nw) ? uwr[ow + t] : -1e30f;
        s_red[t] = uwv; __syncthreads();
        for (int o = 64; o; o >>= 1) { if (t < o) s_red[t] = fmaxf(s_red[t], s_red[t + o]); __syncthreads(); }
        float mx = s_red[0]; __syncthreads();
        float e = (t < nw) ? __expf(uwv - mx) : 0.f;
        s_red[t] = e; __syncthreads();
        for (int o = 64; o; o >>= 1) { if (t < o) s_red[t] += s_red[t + o]; __syncthreads(); }
        float inv = 1.0f / s_red[0]; __syncthreads();
        float w = e * inv;
        s_w[t] = w;
        s_scan[t] = w;
        __syncthreads();
        for (int o = 1; o < 128; o <<= 1) {
            float v = (t >= o) ? s_scan[t - o] : 0.f;
            __syncthreads();
            s_scan[t] += v;
            __syncthreads();
        }
        if (t < nh) {
            float loc = (t == 0) ? 0.f : ((t == nw) ? 1.0f : s_scan[t - 1]);
            float wl = (t >= 1) ? s_w[t - 1] : 0.f;
            float wr = (t <= nw - 1) ? w : 0.f;
            float wwv = 0.5f * (wl + wr);
            float wst = (t < nw) ? w : 0.f;
            g_spl[g * CC + oh + t] = make_float4(uhr[oh + t], wwv, loc, wst);
        }
        __syncthreads();
    }

    s_red[t] = psum; __syncthreads();
    for (int o = 64; o; o >>= 1) { if (t < o) s_red[t] += s_red[t + o]; __syncthreads(); }
    if (t == 0) atomicAdd(&g_acc[1], (double)s_red[0]);
}

// ---------------- K2: scan ----------------
__global__ void k_scan(int G) {
    int t = threadIdx.x, lane = t & 31, w = t >> 5;
    int v = (t < G) ? g_off[t] : 0;
    int s = v;
#pragma unroll
    for (int o = 1; o < 32; o <<= 1) {
        int u = __shfl_up_sync(0xffffffffu, s, o);
        if (lane >= o) s += u;
    }
    __shared__ int ws[16];
    if (lane == 31) ws[w] = s;
    __syncthreads();
    if (w == 0) {
        int x = (lane < 16) ? ws[lane] : 0;
#pragma unroll
        for (int o = 1; o < 16; o <<= 1) {
            int u = __shfl_up_sync(0xffffffffu, x, o);
            if (lane >= o) x += u;
        }
        if (lane < 16) ws[lane] = x;
    }
    __syncthreads();
    int base = (w > 0) ? ws[w - 1] : 0;
    int excl = s + base - v;
    if (t <= G) g_off[t] = excl;
    if (t < G)  g_woff[t] = excl;
}

// ---------------- K3: scatter ----------------
__global__ void k_scatter(const int* __restrict__ lci,
                          const int* __restrict__ lgi,
                          const int* __restrict__ lcgi,
                          const float* __restrict__ coord,
                          int n, int G) {
    int i = blockIdx.x * blockDim.x + threadIdx.x;
    if (i < n) {
        int ci = lci[i];
        int g = ci % G;
        int b = ci / G;
        int p = atomicAdd(&g_woff[g], 1);
        g_cut[p] = make_int4(__float_as_int(coord[i]), lgi[i], b, lcgi[i]);
    }
}

// ---------------- spline step (LDS-based, low registers) ----------------
template <int NH, int OH, int K>
__device__ __forceinline__ void spline_step(const float* __restrict__ s_lw,
                                            const float4* __restrict__ splg,
                                            const float (&cl)[16],
                                            int lane, float& x, float& lad) {
    float uhv[K], wwv[K], locv[K], wv[K];
#pragma unroll
    for (int j = 0; j < K; j++) {
        float4 sp = __ldg(splg + OH + lane * K + j);
        uhv[j] = sp.x; wwv[j] = sp.y; locv[j] = sp.z; wv[j] = sp.w;
    }
    float d[K];
#pragma unroll
    for (int j = 0; j < K; j++) d[j] = 0.f;
#pragma unroll
    for (int l = 0; l < 16; l++) {
        const float* base = s_lw + l * CC + OH + lane * K;
        if constexpr (K == 4) {
            float4 v = *(const float4*)base;
            d[0] = fmaf(cl[l], v.x, d[0]);
            d[1] = fmaf(cl[l], v.y, d[1]);
            d[2] = fmaf(cl[l], v.z, d[2]);
            d[3] = fmaf(cl[l], v.w, d[3]);
        } else if constexpr (K == 2) {
            float2 v = *(const float2*)base;
            d[0] = fmaf(cl[l], v.x, d[0]);
            d[1] = fmaf(cl[l], v.y, d[1]);
        } else {
            d[0] = fmaf(cl[l], *base, d[0]);
        }
    }
    float h[K];
#pragma unroll
    for (int j = 0; j < K; j++) h[j] = __expf(uhv[j] + d[j]);

    int cnt = 0;
#pragma unroll
    for (int j = 0; j < K; j++) cnt += (x >= locv[j]) ? 1 : 0;
    cnt = redux_add(cnt);
    int bin = iminmax(cnt - 1, NH - 2);

    float wprev = __shfl_up_sync(0xffffffffu, wv[K - 1], 1);
    float area = 0.f, cdf = 0.f;
    float wim1 = wprev;
#pragma unroll
    for (int j = 0; j < K; j++) {
        int i = lane * K + j;
        area = fmaf(h[j], wwv[j], area);
        float ct = 0.f;
        if (i < bin) ct += 0.5f * wv[j];
        if (i >= 1 && i <= bin) ct += 0.5f * wim1;
        cdf = fmaf(h[j], ct, cdf);
        wim1 = wv[j];
    }
#pragma unroll
    for (int o = 16; o; o >>= 1) {
        area += __shfl_xor_sync(0xffffffffu, area, o);
        cdf  += __shfl_xor_sync(0xffffffffu, cdf, o);
    }

    int jb  = bin & (K - 1), lb  = bin / K;
    int bp  = bin + 1;
    int jb1 = bp & (K - 1),  lb1 = bp / K;
    float hl_un, hr_un;
    if constexpr (K == 4) {
        hl_un = __shfl_sync(0xffffffffu, sel4(h[0], h[0], h[0], h[0], 0), 0); // placeholder avoided below
    }
    if constexpr (K == 4) {
        hl_un = __shfl_sync(0xffffffffu, sel4(h[0], h[1], h[2], h[3], jb),  lb);
        hr_un = __shfl_sync(0xffffffffu, sel4(h[0], h[1], h[2], h[3], jb1), lb1);
    } else if constexpr (K == 2) {
        hl_un = __shfl_sync(0xffffffffu, sel2(h[0], h[1], jb),  lb);
        hr_un = __shfl_sync(0xffffffffu, sel2(h[0], h[1], jb1), lb1);
    } else {
        hl_un = __shfl_sync(0xffffffffu, h[0], bin);
        hr_un = __shfl_sync(0xffffffffu, h[0], bin + 1);
    }

    float4 spb = __ldg(splg + OH + bin);   // {uh, ww, loc_l, w_b}
    float inv = __fdividef(1.0f, area);
    float hl = hl_un * inv, hr = hr_un * inv, cdfl = cdf * inv;
    float alpha = __fdividef(x - spb.z, spb.w);
    x = (0.5f * (hr - hl) * alpha + hl) * spb.w * alpha + cdfl;
    lad += __logf(fmaf(hr - hl, alpha, hl));
}

// ---------------- K4: main per-cut kernel (2 CTAs per gene, 128 thr) ---------
__global__ void __launch_bounds__(128) k_main(const float* __restrict__ clustering,
                                              int G) {
    __shared__ __align__(16) float s_lw[LL * CC];
    __shared__ double s_acc[4];
    int bid = blockIdx.x, t = threadIdx.x;
    int g = bid >> 1, part = bid & 1;
    int wid = t >> 5, lane = t & 31;

    for (int i = t; i < LL * CC; i += 128) s_lw[i] = g_lw[g * (LL * CC) + i];
    __syncthreads();

    int start = g_off[g], end = g_off[g + 1];
    double acc = 0.0;

    int k = start + part * 4 + wid;
    int4 cd;
    if (k < end) cd = __ldg(&g_cut[k]);

    while (k < end) {
        int kn = k + 8;
        int4 cdn;
        if (kn < end) cdn = __ldg(&g_cut[kn]);

        float x = __int_as_float(cd.x);
        int gl = cd.y, b = cd.z;

        const float4* splg = g_spl + (size_t)gl * CC;
        const float4* cp = (const float4*)(clustering + (size_t)b * LL);
        float4 c0 = cp[0], c1 = cp[1], c2 = cp[2], c3 = cp[3];
        float cl[16] = {c0.x, c0.y, c0.z, c0.w, c1.x, c1.y, c1.z, c1.w,
                        c2.x, c2.y, c2.z, c2.w, c3.x, c3.y, c3.z, c3.w};

        float lad = 0.f;
        spline_step<128, 0,   4>(s_lw, splg, cl, lane, x, lad);
        spline_step<64,  128, 2>(s_lw, splg, cl, lane, x, lad);
        spline_step<32,  192, 1>(s_lw, splg, cl, lane, x, lad);

        if (lane == 0) acc += (double)lad;
        cd = cdn;
        k = kn;
    }

    if (lane == 0) s_acc[wid] = acc;
    __syncthreads();
    if (t == 0) {
        double tot = s_acc[0] + s_acc[1] + s_acc[2] + s_acc[3];
        atomicAdd(&g_acc[0], tot);
    }
}

// ---------------- K5: z ----------------
__global__ void k_z(const float* __restrict__ clustering,
                    const float* __restrict__ rho_weight,
                    const float* __restrict__ rho_bias, int GT) {
    int j = blockIdx.x * blockDim.x + threadIdx.x;
    if (j >= GT) return;
    int b0 = blockIdx.y * 8;
    float lb = __logf(rho_bias[j]);
    const float4* rw = (const float4*)(rho_weight + (size_t)j * LL);
    float4 r0 = rw[0], r1 = rw[1], r2 = rw[2], r3 = rw[3];
#pragma unroll
    for (int bi = 0; bi < 8; bi++) {
        int b = b0 + bi;
        const float4* cp = (const float4*)(clustering + (size_t)b * LL);
        float4 c0 = cp[0], c1 = cp[1], c2 = cp[2], c3 = cp[3];
        float z = lb;
        z = fmaf(c0.x, r0.x, z); z = fmaf(c0.y, r0.y, z); z = fmaf(c0.z, r0.z, z); z = fmaf(c0.w, r0.w, z);
        z = fmaf(c1.x, r1.x, z); z = fmaf(c1.y, r1.y, z); z = fmaf(c1.z, r1.z, z); z = fmaf(c1.w, r1.w, z);
        z = fmaf(c2.x, r2.x, z); z = fmaf(c2.y, r2.y, z); z = fmaf(c2.z, r2.z, z); z = fmaf(c2.w, r2.w, z);
        z = fmaf(c3.x, r3.x, z); z = fmaf(c3.y, r3.y, z); z = fmaf(c3.z, r3.z, z); z = fmaf(c3.w, r3.w, z);
        g_z[(size_t)b * GT + j] = z;
    }
}

// ---------------- K6: logsumexp ----------------
__global__ void k_lse(int GT) {
    int b = blockIdx.x, t = threadIdx.x;
    const float* zr = g_z + (size_t)b * GT;
    float m = -1e30f, s = 0.f;
    for (int j = t; j < GT; j += blockDim.x) {
        float v = zr[j];
        if (v > m) { s = s * __expf(m - v) + 1.f; m = v; }
        else       { s += __expf(v - m); }
    }
    __shared__ float sm[256], ss[256];
    sm[t] = m; ss[t] = s; __syncthreads();
    for (int o = 128; o; o >>= 1) {
        if (t < o) {
            float m1 = sm[t], s1 = ss[t], m2 = sm[t + o], s2 = ss[t + o];
            float M = fmaxf(m1, m2);
            sm[t] = M;
            ss[t] = s1 * __expf(m1 - M) + s2 * __expf(m2 - M);
        }
        __syncthreads();
    }
    if (t == 0) g_logZ[b] = sm[0] + logf(ss[0]);
}

// ---------------- K7: rho gather-sum over cuts ----------------
__global__ void k_rho(const int* __restrict__ lcgi, int n, int GT) {
    int i = blockIdx.x * blockDim.x + threadIdx.x;
    float v = 0.f;
    if (i < n) {
        int li = lcgi[i];
        v = __ldg(&g_z[li]) - __ldg(&g_logZ[li / GT]);
    }
    // block reduction in double
    __shared__ double sd[256];
    sd[threadIdx.x] = (double)v;
    __syncthreads();
    for (int o = 128; o; o >>= 1) {
        if (threadIdx.x < o) sd[threadIdx.x] += sd[threadIdx.x + o];
        __syncthreads();
    }
    if (threadIdx.x == 0) atomicAdd(&g_acc[0], sd[0]);
}

// ---------------- K8: finalize + restore state for next replay ----------------
__global__ void k_final(float* out, int G, int N, float logGT) {
    int t = threadIdx.x;
    if (t == 0) {
        double cnt = (double)G * (double)(LL * CC + LL);
        out[0] = (float)(-g_acc[0] - (double)N * (double)logGT
                         - g_acc[1] + 0.5 * LOG2PI * cnt);
    }
    __syncthreads();
    // restore zero state so the next graph replay starts clean
    for (int i = t; i <= G; i += blockDim.x) g_off[i] = 0;
    if (t < 2) g_acc[t] = 0.0;
}

// ---------------- launch ----------------
extern "C" void kernel_launch(void* const* d_in, const int* in_sizes, int n_in,
                              void* d_out, int out_size) {
    const float* clustering    = (const float*)d_in[0];
    const float* coordinates   = (const float*)d_in[1];
    const int*   genes_oi      = (const int*)d_in[2];
    const int*   local_gene_ix = (const int*)d_in[3];
    const int*   lci           = (const int*)d_in[4];
    const int*   lcgi          = (const int*)d_in[5];
    const float* logit_weight  = (const float*)d_in[6];
    const float* rho_weight    = (const float*)d_in[7];
    const float* rho_bias      = (const float*)d_in[8];
    const float* uh            = (const float*)d_in[9];
    const float* uw            = (const float*)d_in[10];

    int N  = in_sizes[1];
    int G  = in_sizes[2];
    int B  = in_sizes[0] / LL;
    int GT = in_sizes[8];

    int histBlocks = (N + 127) / 128;
    k_pergene_hist<<<G + histBlocks, 128>>>(genes_oi, logit_weight, rho_weight,
                                            uh, uw, lci, N, G);
    k_scan<<<1, 512>>>(G);
    k_scatter<<<(N + 255) / 256, 256>>>(lci, local_gene_ix, lcgi, coordinates, N, G);
    k_main<<<2 * G, 128>>>(clustering, G);
    k_z<<<dim3((GT + 255) / 256, B / 8), 256>>>(clustering, rho_weight, rho_bias, GT);
    k_lse<<<B, 256>>>(GT);
    k_rho<<<(N + 255) / 256, 256>>>(lcgi, N, GT);
    k_final<<<1, 512>>>((float*)d_out, G, N, logf((float)GT));
}

// round 4
// speedup vs baseline: 1.2708x; 1.1103x over previous
#include <cuda_runtime.h>
#include <math.h>
#include <stdint.h>

#define NCUT 200000
#define GOI  500
#define BB   512
#define LL   16
#define CC   224
#define GTOT 20000
#define LOG2PI 1.8378770664093453
#define NPART 3
#define SDS   236   // per-cut d stride in floats (16B aligned, conflict-free)

// ---------------- device scratch (zero at load; k_final restores) ----------
__device__ float  g_lw[GOI * LL * CC];
__device__ float4 g_spl[GOI * CC];       // PERMUTED layout per step (see k_pergene)
__device__ float  g_z[BB * GTOT];
__device__ float  g_logZ[BB];
__device__ int    g_off[GOI + 1];
__device__ int    g_woff[GOI];
__device__ int4   g_cut[NCUT];           // {x_bits, gl, b, li}
__device__ double g_acc[2];

// ---------------- helpers ----------------
__device__ __forceinline__ unsigned long long pk(float a, float b) {
    unsigned long long r;
    asm("mov.b64 %0, {%1,%2};" : "=l"(r) : "f"(a), "f"(b));
    return r;
}
__device__ __forceinline__ void fma2(unsigned long long& d, unsigned long long a, unsigned long long b) {
    asm("fma.rn.f32x2 %0, %1, %2, %0;" : "+l"(d) : "l"(a), "l"(b));
}
__device__ __forceinline__ int redux_add(int v) {
    int r;
    asm("redux.sync.add.s32 %0, %1, 0xffffffff;" : "=r"(r) : "r"(v));
    return r;
}
__device__ __forceinline__ float sel4(float a, float b, float c, float d, int j) {
    float lo = (j & 1) ? b : a;
    float hi = (j & 1) ? d : c;
    return (j & 2) ? hi : lo;
}
__device__ __forceinline__ float sel2(float a, float b, int j) { return j ? b : a; }
__device__ __forceinline__ int iminmax(int v, int hi) { v = v < 0 ? 0 : v; return v > hi ? hi : v; }

// ---------------- K1: fused per-gene precompute + histogram ----------------
__global__ void k_pergene_hist(const int* __restrict__ genes_oi,
                               const float* __restrict__ logit_weight,
                               const float* __restrict__ rho_weight,
                               const float* __restrict__ uh,
                               const float* __restrict__ uw,
                               const int* __restrict__ lci,
                               int n, int G) {
    int bid = blockIdx.x, t = threadIdx.x;
    if (bid >= G) {
        int i = (bid - G) * 128 + t;
        if (i < n) atomicAdd(&g_off[lci[i] % G], 1);
        return;
    }
    int g = bid;
    int gene = genes_oi[g];

    float psum = 0.f;
    const float* lwr = logit_weight + (size_t)gene * (LL * CC);
    for (int i = t; i < LL * CC; i += 128) {
        float v = lwr[i];
        g_lw[g * (LL * CC) + i] = v;
        psum -= 0.5f * v * v;
    }
    if (t < LL) { float v = rho_weight[gene * LL + t]; psum -= 0.5f * v * v; }

    __shared__ float s_red[128];
    __shared__ float s_w[128];
    __shared__ float s_scan[128];

    const int nh_t[3] = {128, 64, 32};
    const int oh_t[3] = {0, 128, 192};
    const int ow_t[3] = {0, 127, 190};
    const float* uhr = uh + (size_t)gene * CC;
    const float* uwr = uw + (size_t)gene * 221;

    for (int s = 0; s < 3; s++) {
        int nh = nh_t[s], nw = nh - 1, oh = oh_t[s], ow = ow_t[s];
        float uwv = (t < nw) ? uwr[ow + t] : -1e30f;
        s_red[t] = uwv; __syncthreads();
        for (int o = 64; o; o >>= 1) { if (t < o) s_red[t] = fmaxf(s_red[t], s_red[t + o]); __syncthreads(); }
        float mx = s_red[0]; __syncthreads();
        float e = (t < nw) ? __expf(uwv - mx) : 0.f;
        s_red[t] = e; __syncthreads();
        for (int o = 64; o; o >>= 1) { if (t < o) s_red[t] += s_red[t + o]; __syncthreads(); }
        float inv = 1.0f / s_red[0]; __syncthreads();
        float w = e * inv;
        s_w[t] = w;
        s_scan[t] = w;
        __syncthreads();
        for (int o = 1; o < 128; o <<= 1) {
            float v = (t >= o) ? s_scan[t - o] : 0.f;
            __syncthreads();
            s_scan[t] += v;
            __syncthreads();
        }
        if (t < nh) {
            float loc = (t == 0) ? 0.f : ((t == nw) ? 1.0f : s_scan[t - 1]);
            float wl = (t >= 1) ? s_w[t - 1] : 0.f;
            float wr = (t <= nw - 1) ? w : 0.f;
            float wwv = 0.5f * (wl + wr);
            float wst = (t < nw) ? w : 0.f;
            // permuted store for coalesced main-kernel loads:
            int pos;
            if (s == 0)      pos = (t & 3) * 32 + (t >> 2);        // height i at j*32+r, i=4r+j
            else if (s == 1) pos = 128 + (t & 1) * 32 + (t >> 1);  // i=2r+j
            else             pos = 192 + t;
            g_spl[g * CC + pos] = make_float4(uhr[oh + t], wwv, loc, wst);
        }
        __syncthreads();
    }

    s_red[t] = psum; __syncthreads();
    for (int o = 64; o; o >>= 1) { if (t < o) s_red[t] += s_red[t + o]; __syncthreads(); }
    if (t == 0) atomicAdd(&g_acc[1], (double)s_red[0]);
}

// ---------------- K2: scan ----------------
__global__ void k_scan(int G) {
    int t = threadIdx.x, lane = t & 31, w = t >> 5;
    int v = (t < G) ? g_off[t] : 0;
    int s = v;
#pragma unroll
    for (int o = 1; o < 32; o <<= 1) {
        int u = __shfl_up_sync(0xffffffffu, s, o);
        if (lane >= o) s += u;
    }
    __shared__ int ws[16];
    if (lane == 31) ws[w] = s;
    __syncthreads();
    if (w == 0) {
        int x = (lane < 16) ? ws[lane] : 0;
#pragma unroll
        for (int o = 1; o < 16; o <<= 1) {
            int u = __shfl_up_sync(0xffffffffu, x, o);
            if (lane >= o) x += u;
        }
        if (lane < 16) ws[lane] = x;
    }
    __syncthreads();
    int base = (w > 0) ? ws[w - 1] : 0;
    int excl = s + base - v;
    if (t <= G) g_off[t] = excl;
    if (t < G)  g_woff[t] = excl;
}

// ---------------- K3: scatter ----------------
__global__ void k_scatter(const int* __restrict__ lci,
                          const int* __restrict__ lgi,
                          const int* __restrict__ lcgi,
                          const float* __restrict__ coord,
                          int n, int G) {
    int i = blockIdx.x * blockDim.x + threadIdx.x;
    if (i < n) {
        int ci = lci[i];
        int g = ci % G;
        int b = ci / G;
        int p = atomicAdd(&g_woff[g], 1);
        g_cut[p] = make_int4(__float_as_int(coord[i]), lgi[i], b, lcgi[i]);
    }
}

// ---------------- K4: main per-cut kernel ----------------
// Phase A: 8 cuts per warp, lane = (cut c = lane>>2, quarter sub = lane&3);
//          each lane computes 56 of 224 delta values for its cut -> smem.
// Phase B: warp-parallel spline eval per cut, coalesced permuted g_spl loads.
__global__ void __launch_bounds__(128) k_main(const float* __restrict__ clustering,
                                              int G) {
    __shared__ __align__(16) float s_lw[LL * CC];      // 14336 B
    __shared__ __align__(16) float s_d[4 * 8 * SDS];   // 30208 B
    __shared__ double s_acc[4];
    const unsigned FULL = 0xffffffffu;

    int bid = blockIdx.x, t = threadIdx.x;
    int g = bid / NPART, part = bid - g * NPART;
    int wid = t >> 5, lane = t & 31;
    int c = lane >> 2, sub = lane & 3;

    for (int i = t; i < LL * CC; i += 128) s_lw[i] = g_lw[g * (LL * CC) + i];
    __syncthreads();

    int s0 = g_off[g], e0 = g_off[g + 1];
    int tot = e0 - s0;
    int seg = (tot + NPART - 1) / NPART;
    int mystart = s0 + part * seg;
    int myend = mystart + seg; if (myend > e0) myend = e0;

    float* sd = s_d + wid * (8 * SDS);
    double acc = 0.0;

    for (int base = mystart + wid * 8; base < myend; base += 32) {
        int nc = myend - base; if (nc > 8) nc = 8;

        // ---- Phase A ----
        int myk = base + c;
        int4 cd = make_int4(0, 0, 0, 0);
        if (myk < myend) cd = __ldg(&g_cut[myk]);

        const float4* cp = (const float4*)(clustering + (size_t)cd.z * LL);
        float4 c0 = __ldg(cp + 0), c1 = __ldg(cp + 1), c2 = __ldg(cp + 2), c3 = __ldg(cp + 3);
        unsigned long long cpk[16];
        cpk[0]  = pk(c0.x, c0.x); cpk[1]  = pk(c0.y, c0.y); cpk[2]  = pk(c0.z, c0.z); cpk[3]  = pk(c0.w, c0.w);
        cpk[4]  = pk(c1.x, c1.x); cpk[5]  = pk(c1.y, c1.y); cpk[6]  = pk(c1.z, c1.z); cpk[7]  = pk(c1.w, c1.w);
        cpk[8]  = pk(c2.x, c2.x); cpk[9]  = pk(c2.y, c2.y); cpk[10] = pk(c2.z, c2.z); cpk[11] = pk(c2.w, c2.w);
        cpk[12] = pk(c3.x, c3.x); cpk[13] = pk(c3.y, c3.y); cpk[14] = pk(c3.z, c3.z); cpk[15] = pk(c3.w, c3.w);

        const ulonglong2* lwv = (const ulonglong2*)s_lw;
        for (int chk = 0; chk < 14; chk++) {
            int i4 = sub * 14 + chk;
            unsigned long long a01 = 0ull, a23 = 0ull;
#pragma unroll
            for (int l = 0; l < 16; l++) {
                ulonglong2 v = lwv[l * 56 + i4];
                fma2(a01, cpk[l], v.x);
                fma2(a23, cpk[l], v.y);
            }
            *(ulonglong2*)&sd[c * SDS + (i4 << 2)] = make_ulonglong2(a01, a23);
        }
        __syncwarp();

        // ---- Phase B ----
        for (int cc = 0; cc < nc; cc++) {
            int srcl = cc << 2;
            float x = __shfl_sync(FULL, __int_as_float(cd.x), srcl);
            int gl = __shfl_sync(FULL, cd.y, srcl);
            const float4* splg = g_spl + (size_t)gl * CC;
            const float* dd = sd + cc * SDS;
            float lad = 0.f;

            // ===== step 1: 128 heights, lane owns i = 4*lane+j =====
            {
                float4 p0 = __ldg(splg + lane);
                float4 p1 = __ldg(splg + 32 + lane);
                float4 p2 = __ldg(splg + 64 + lane);
                float4 p3 = __ldg(splg + 96 + lane);
                float4 d4 = *(const float4*)&dd[lane << 2];
                float h0 = __expf(p0.x + d4.x), h1 = __expf(p1.x + d4.y);
                float h2 = __expf(p2.x + d4.z), h3 = __expf(p3.x + d4.w);

                int cnt = (x >= p0.z) + (x >= p1.z) + (x >= p2.z) + (x >= p3.z);
                cnt = redux_add(cnt);
                int bin = iminmax(cnt - 1, 126);

                float wprev = __shfl_up_sync(FULL, p3.w, 1);
                int i0 = lane << 2;
                float area = h0 * p0.y;
                area = fmaf(h1, p1.y, area); area = fmaf(h2, p2.y, area); area = fmaf(h3, p3.y, area);
                float ct0 = ((i0 < bin) ? 0.5f * p0.w : 0.f) + ((i0 >= 1 && i0 <= bin) ? 0.5f * wprev : 0.f);
                float ct1 = ((i0 + 1 < bin) ? 0.5f * p1.w : 0.f) + ((i0 + 1 <= bin) ? 0.5f * p0.w : 0.f);
                float ct2 = ((i0 + 2 < bin) ? 0.5f * p2.w : 0.f) + ((i0 + 2 <= bin) ? 0.5f * p1.w : 0.f);
                float ct3 = ((i0 + 3 < bin) ? 0.5f * p3.w : 0.f) + ((i0 + 3 <= bin) ? 0.5f * p2.w : 0.f);
                float cdf = h0 * ct0;
                cdf = fmaf(h1, ct1, cdf); cdf = fmaf(h2, ct2, cdf); cdf = fmaf(h3, ct3, cdf);
#pragma unroll
                for (int o = 16; o; o >>= 1) {
                    area += __shfl_xor_sync(FULL, area, o);
                    cdf  += __shfl_xor_sync(FULL, cdf, o);
                }
                int jb = bin & 3, lb = bin >> 2;
                int jb1 = (bin + 1) & 3, lb1 = (bin + 1) >> 2;
                float hl   = __shfl_sync(FULL, sel4(h0, h1, h2, h3, jb),  lb);
                float hr   = __shfl_sync(FULL, sel4(h0, h1, h2, h3, jb1), lb1);
                float locl = __shfl_sync(FULL, sel4(p0.z, p1.z, p2.z, p3.z, jb), lb);
                float wb   = __shfl_sync(FULL, sel4(p0.w, p1.w, p2.w, p3.w, jb), lb);
                float inv = __fdividef(1.f, area);
                float alpha = __fdividef(x - locl, wb);
                float hln = hl * inv, hrn = hr * inv;
                x = (0.5f * (hrn - hln) * alpha + hln) * wb * alpha + cdf * inv;
                lad += __logf(fmaf(hrn - hln, alpha, hln));
            }

            // ===== step 2: 64 heights, lane owns i = 2*lane+j =====
            {
                float4 q0 = __ldg(splg + 128 + lane);
                float4 q1 = __ldg(splg + 160 + lane);
                float2 d2 = *(const float2*)&dd[128 + (lane << 1)];
                float h0 = __expf(q0.x + d2.x), h1 = __expf(q1.x + d2.y);

                int cnt = (x >= q0.z) + (x >= q1.z);
                cnt = redux_add(cnt);
                int bin = iminmax(cnt - 1, 62);

                float wprev = __shfl_up_sync(FULL, q1.w, 1);
                int i0 = lane << 1;
                float area = fmaf(h1, q1.y, h0 * q0.y);
                float ct0 = ((i0 < bin) ? 0.5f * q0.w : 0.f) + ((i0 >= 1 && i0 <= bin) ? 0.5f * wprev : 0.f);
                float ct1 = ((i0 + 1 < bin) ? 0.5f * q1.w : 0.f) + ((i0 + 1 <= bin) ? 0.5f * q0.w : 0.f);
                float cdf = fmaf(h1, ct1, h0 * ct0);
#pragma unroll
                for (int o = 16; o; o >>= 1) {
                    area += __shfl_xor_sync(FULL, area, o);
                    cdf  += __shfl_xor_sync(FULL, cdf, o);
                }
                int jb = bin & 1, lb = bin >> 1;
                int jb1 = (bin + 1) & 1, lb1 = (bin + 1) >> 1;
                float hl   = __shfl_sync(FULL, sel2(h0, h1, jb),  lb);
                float hr   = __shfl_sync(FULL, sel2(h0, h1, jb1), lb1);
                float locl = __shfl_sync(FULL, sel2(q0.z, q1.z, jb), lb);
                float wb   = __shfl_sync(FULL, sel2(q0.w, q1.w, jb), lb);
                float inv = __fdividef(1.f, area);
                float alpha = __fdividef(x - locl, wb);
                float hln = hl * inv, hrn = hr * inv;
                x = (0.5f * (hrn - hln) * alpha + hln) * wb * alpha + cdf * inv;
                lad += __logf(fmaf(hrn - hln, alpha, hln));
            }

            // ===== step 3: 32 heights, lane owns i = lane =====
            {
                float4 r0 = __ldg(splg + 192 + lane);
                float ds = dd[192 + lane];
                float h0 = __expf(r0.x + ds);

                int cnt = (x >= r0.z) ? 1 : 0;
                cnt = redux_add(cnt);
                int bin = iminmax(cnt - 1, 30);

                float wprev = __shfl_up_sync(FULL, r0.w, 1);
                float area = h0 * r0.y;
                float ct0 = ((lane < bin) ? 0.5f * r0.w : 0.f) + ((lane >= 1 && lane <= bin) ? 0.5f * wprev : 0.f);
                float cdf = h0 * ct0;
#pragma unroll
                for (int o = 16; o; o >>= 1) {
                    area += __shfl_xor_sync(FULL, area, o);
                    cdf  += __shfl_xor_sync(FULL, cdf, o);
                }
                float hl   = __shfl_sync(FULL, h0, bin);
                float hr   = __shfl_sync(FULL, h0, bin + 1);
                float locl = __shfl_sync(FULL, r0.z, bin);
                float wb   = __shfl_sync(FULL, r0.w, bin);
                float inv = __fdividef(1.f, area);
                float alpha = __fdividef(x - locl, wb);
                float hln = hl * inv, hrn = hr * inv;
                x = (0.5f * (hrn - hln) * alpha + hln) * wb * alpha + cdf * inv;
                lad += __logf(fmaf(hrn - hln, alpha, hln));
            }

            if (lane == 0) acc += (double)lad;
        }
        __syncwarp();
    }

    if (lane == 0) s_acc[wid] = acc;
    __syncthreads();
    if (t == 0) {
        double tt = s_acc[0] + s_acc[1] + s_acc[2] + s_acc[3];
        atomicAdd(&g_acc[0], tt);
    }
}

// ---------------- K5: z ----------------
__global__ void k_z(const float* __restrict__ clustering,
                    const float* __restrict__ rho_weight,
                    const float* __restrict__ rho_bias, int GT) {
    int j = blockIdx.x * blockDim.x + threadIdx.x;
    if (j >= GT) return;
    int b0 = blockIdx.y * 8;
    float lb = __logf(rho_bias[j]);
    const float4* rw = (const float4*)(rho_weight + (size_t)j * LL);
    float4 r0 = rw[0], r1 = rw[1], r2 = rw[2], r3 = rw[3];
#pragma unroll
    for (int bi = 0; bi < 8; bi++) {
        int b = b0 + bi;
        const float4* cp = (const float4*)(clustering + (size_t)b * LL);
        float4 c0 = cp[0], c1 = cp[1], c2 = cp[2], c3 = cp[3];
        float z = lb;
        z = fmaf(c0.x, r0.x, z); z = fmaf(c0.y, r0.y, z); z = fmaf(c0.z, r0.z, z); z = fmaf(c0.w, r0.w, z);
        z = fmaf(c1.x, r1.x, z); z = fmaf(c1.y, r1.y, z); z = fmaf(c1.z, r1.z, z); z = fmaf(c1.w, r1.w, z);
        z = fmaf(c2.x, r2.x, z); z = fmaf(c2.y, r2.y, z); z = fmaf(c2.z, r2.z, z); z = fmaf(c2.w, r2.w, z);
        z = fmaf(c3.x, r3.x, z); z = fmaf(c3.y, r3.y, z); z = fmaf(c3.z, r3.z, z); z = fmaf(c3.w, r3.w, z);
        g_z[(size_t)b * GT + j] = z;
    }
}

// ---------------- K6: logsumexp ----------------
__global__ void k_lse(int GT) {
    int b = blockIdx.x, t = threadIdx.x;
    const float* zr = g_z + (size_t)b * GT;
    float m = -1e30f, s = 0.f;
    for (int j = t; j < GT; j += blockDim.x) {
        float v = zr[j];
        if (v > m) { s = s * __expf(m - v) + 1.f; m = v; }
        else       { s += __expf(v - m); }
    }
    __shared__ float sm[256], ss[256];
    sm[t] = m; ss[t] = s; __syncthreads();
    for (int o = 128; o; o >>= 1) {
        if (t < o) {
            float m1 = sm[t], s1 = ss[t], m2 = sm[t + o], s2 = ss[t + o];
            float M = fmaxf(m1, m2);
            sm[t] = M;
            ss[t] = s1 * __expf(m1 - M) + s2 * __expf(m2 - M);
        }
        __syncthreads();
    }
    if (t == 0) g_logZ[b] = sm[0] + logf(ss[0]);
}

// ---------------- K7: rho gather-sum ----------------
__global__ void k_rho(const int* __restrict__ lcgi, int n, int GT) {
    int i = blockIdx.x * blockDim.x + threadIdx.x;
    float v = 0.f;
    if (i < n) {
        int li = lcgi[i];
        v = __ldg(&g_z[li]) - __ldg(&g_logZ[li / GT]);
    }
    __shared__ double sd_[256];
    sd_[threadIdx.x] = (double)v;
    __syncthreads();
    for (int o = 128; o; o >>= 1) {
        if (threadIdx.x < o) sd_[threadIdx.x] += sd_[threadIdx.x + o];
        __syncthreads();
    }
    if (threadIdx.x == 0) atomicAdd(&g_acc[0], sd_[0]);
}

// ---------------- K8: finalize + restore ----------------
__global__ void k_final(float* out, int G, int N, float logGT) {
    int t = threadIdx.x;
    if (t == 0) {
        double cnt = (double)G * (double)(LL * CC + LL);
        out[0] = (float)(-g_acc[0] - (double)N * (double)logGT
                         - g_acc[1] + 0.5 * LOG2PI * cnt);
    }
    __syncthreads();
    for (int i = t; i <= G; i += blockDim.x) g_off[i] = 0;
    if (t < 2) g_acc[t] = 0.0;
}

// ---------------- launch ----------------
extern "C" void kernel_launch(void* const* d_in, const int* in_sizes, int n_in,
                              void* d_out, int out_size) {
    const float* clustering    = (const float*)d_in[0];
    const float* coordinates   = (const float*)d_in[1];
    const int*   genes_oi      = (const int*)d_in[2];
    const int*   local_gene_ix = (const int*)d_in[3];
    const int*   lci           = (const int*)d_in[4];
    const int*   lcgi          = (const int*)d_in[5];
    const float* logit_weight  = (const float*)d_in[6];
    const float* rho_weight    = (const float*)d_in[7];
    const float* rho_bias      = (const float*)d_in[8];
    const float* uh            = (const float*)d_in[9];
    const float* uw            = (const float*)d_in[10];

    int N  = in_sizes[1];
    int G  = in_sizes[2];
    int B  = in_sizes[0] / LL;
    int GT = in_sizes[8];

    int histBlocks = (N + 127) / 128;
    k_pergene_hist<<<G + histBlocks, 128>>>(genes_oi, logit_weight, rho_weight,
                                            uh, uw, lci, N, G);
    k_scan<<<1, 512>>>(G);
    k_scatter<<<(N + 255) / 256, 256>>>(lci, local_gene_ix, lcgi, coordinates, N, G);
    k_main<<<NPART * G, 128>>>(clustering, G);
    k_z<<<dim3((GT + 255) / 256, B / 8), 256>>>(clustering, rho_weight, rho_bias, GT);
    k_lse<<<B, 256>>>(GT);
    k_rho<<<(N + 255) / 256, 256>>>(lcgi, N, GT);
    k_final<<<1, 512>>>((float*)d_out, G, N, logf((float)GT));
}

// round 5
// speedup vs baseline: 1.2801x; 1.0073x over previous
#include <cuda_runtime.h>
#include <math.h>
#include <stdint.h>

#define NCUT 200000
#define GOI  500
#define BB   512
#define LL   16
#define CC   224
#define GTOT 20000
#define LOG2PI 1.8378770664093453
#define NPART 3
#define SDS   292   // padded per-cut d stride in floats

// dynamic smem bytes for k_main: lw tile + 4 warps * 8 cuts * SDS floats
#define KMAIN_SMEM ((LL * CC + 4 * 8 * SDS) * 4)

// ---------------- device scratch (zero at load; k_final restores) ----------
__device__ float  g_lw[GOI * LL * CC];
__device__ float4 g_spl[GOI * CC];       // PERMUTED per-step (see k_pergene)
__device__ float  g_z[BB * GTOT];
__device__ float  g_logZ[BB];
__device__ int    g_off[GOI + 1];
__device__ int    g_woff[GOI];
__device__ int4   g_cut[NCUT];           // {x_bits, gl, b, li}
__device__ double g_acc[2];

// ---------------- helpers ----------------
__device__ __forceinline__ unsigned long long pk(float a, float b) {
    unsigned long long r;
    asm("mov.b64 %0, {%1,%2};" : "=l"(r) : "f"(a), "f"(b));
    return r;
}
__device__ __forceinline__ void fma2(unsigned long long& d, unsigned long long a, unsigned long long b) {
    asm("fma.rn.f32x2 %0, %1, %2, %0;" : "+l"(d) : "l"(a), "l"(b));
}
__device__ __forceinline__ int iminmax(int v, int hi) { v = v < 0 ? 0 : v; return v > hi ? hi : v; }

// d-array padded position of float index i (i in [0,224))
__device__ __forceinline__ int posd1(int i)  { return (i >> 4) * 20 + (i & 15); }         // step1 i<128
__device__ __forceinline__ int posd2(int i2) { return 160 + (i2 >> 3) * 12 + (i2 & 7); }  // step2 local
__device__ __forceinline__ int posd3(int i3) { return 256 + i3; }                          // step3 local
__device__ __forceinline__ int pos4(int i4) {  // float offset of i = 4*i4 (Phase A stores)
    if (i4 < 32) return (i4 >> 2) * 20 + ((i4 & 3) << 2);
    if (i4 < 48) return 160 + ((i4 - 32) >> 1) * 12 + ((i4 & 1) << 2);
    return 256 + ((i4 - 48) << 2);
}

// ---------------- K1: fused per-gene precompute + histogram ----------------
__global__ void k_pergene_hist(const int* __restrict__ genes_oi,
                               const float* __restrict__ logit_weight,
                               const float* __restrict__ rho_weight,
                               const float* __restrict__ uh,
                               const float* __restrict__ uw,
                               const int* __restrict__ lci,
                               int n, int G) {
    int bid = blockIdx.x, t = threadIdx.x;
    if (bid >= G) {
        int i = (bid - G) * 128 + t;
        if (i < n) atomicAdd(&g_off[lci[i] % G], 1);
        return;
    }
    int g = bid;
    int gene = genes_oi[g];

    float psum = 0.f;
    const float* lwr = logit_weight + (size_t)gene * (LL * CC);
    for (int i = t; i < LL * CC; i += 128) {
        float v = lwr[i];
        g_lw[g * (LL * CC) + i] = v;
        psum -= 0.5f * v * v;
    }
    if (t < LL) { float v = rho_weight[gene * LL + t]; psum -= 0.5f * v * v; }

    __shared__ float s_red[128];
    __shared__ float s_w[128];
    __shared__ float s_scan[128];

    const int nh_t[3] = {128, 64, 32};
    const int oh_t[3] = {0, 128, 192};
    const int ow_t[3] = {0, 127, 190};
    const float* uhr = uh + (size_t)gene * CC;
    const float* uwr = uw + (size_t)gene * 221;

    for (int s = 0; s < 3; s++) {
        int nh = nh_t[s], nw = nh - 1, oh = oh_t[s], ow = ow_t[s];
        float uwv = (t < nw) ? uwr[ow + t] : -1e30f;
        s_red[t] = uwv; __syncthreads();
        for (int o = 64; o; o >>= 1) { if (t < o) s_red[t] = fmaxf(s_red[t], s_red[t + o]); __syncthreads(); }
        float mx = s_red[0]; __syncthreads();
        float e = (t < nw) ? __expf(uwv - mx) : 0.f;
        s_red[t] = e; __syncthreads();
        for (int o = 64; o; o >>= 1) { if (t < o) s_red[t] += s_red[t + o]; __syncthreads(); }
        float inv = 1.0f / s_red[0]; __syncthreads();
        float w = e * inv;
        s_w[t] = w;
        s_scan[t] = w;
        __syncthreads();
        for (int o = 1; o < 128; o <<= 1) {
            float v = (t >= o) ? s_scan[t - o] : 0.f;
            __syncthreads();
            s_scan[t] += v;
            __syncthreads();
        }
        if (t < nh) {
            float loc = (t == 0) ? 0.f : ((t == nw) ? 1.0f : s_scan[t - 1]);
            float wl = (t >= 1) ? s_w[t - 1] : 0.f;
            float wr = (t <= nw - 1) ? w : 0.f;
            float wwv = 0.5f * (wl + wr);
            float wst = (t < nw) ? w : 0.f;
            // permuted for 8-lane quarter access: slot = j*8 + ll
            int pos;
            if (s == 0)      pos = (t & 15) * 8 + (t >> 4);
            else if (s == 1) pos = 128 + (t & 7) * 8 + (t >> 3);
            else             pos = 192 + (t & 3) * 8 + (t >> 2);
            g_spl[g * CC + pos] = make_float4(uhr[oh + t], wwv, loc, wst);
        }
        __syncthreads();
    }

    s_red[t] = psum; __syncthreads();
    for (int o = 64; o; o >>= 1) { if (t < o) s_red[t] += s_red[t + o]; __syncthreads(); }
    if (t == 0) atomicAdd(&g_acc[1], (double)s_red[0]);
}

// ---------------- K2: scan ----------------
__global__ void k_scan(int G) {
    int t = threadIdx.x, lane = t & 31, w = t >> 5;
    int v = (t < G) ? g_off[t] : 0;
    int s = v;
#pragma unroll
    for (int o = 1; o < 32; o <<= 1) {
        int u = __shfl_up_sync(0xffffffffu, s, o);
        if (lane >= o) s += u;
    }
    __shared__ int ws[16];
    if (lane == 31) ws[w] = s;
    __syncthreads();
    if (w == 0) {
        int x = (lane < 16) ? ws[lane] : 0;
#pragma unroll
        for (int o = 1; o < 16; o <<= 1) {
            int u = __shfl_up_sync(0xffffffffu, x, o);
            if (lane >= o) x += u;
        }
        if (lane < 16) ws[lane] = x;
    }
    __syncthreads();
    int base = (w > 0) ? ws[w - 1] : 0;
    int excl = s + base - v;
    if (t <= G) g_off[t] = excl;
    if (t < G)  g_woff[t] = excl;
}

// ---------------- K3: scatter ----------------
__global__ void k_scatter(const int* __restrict__ lci,
                          const int* __restrict__ lgi,
                          const int* __restrict__ lcgi,
                          const float* __restrict__ coord,
                          int n, int G) {
    int i = blockIdx.x * blockDim.x + threadIdx.x;
    if (i < n) {
        int ci = lci[i];
        int g = ci % G;
        int b = ci / G;
        int p = atomicAdd(&g_woff[g], 1);
        g_cut[p] = make_int4(__float_as_int(coord[i]), lgi[i], b, lcgi[i]);
    }
}

// ---------------- K4: main per-cut kernel ----------------
// Phase A: 8 cuts per warp, lane (c=lane>>2, sub=lane&3) -> d values to padded smem.
// Phase B: 2 passes x 4 quarter-warps; each 8-lane quarter evaluates one cut.
__global__ void __launch_bounds__(128) k_main(const float* __restrict__ clustering,
                                              int G) {
    extern __shared__ __align__(16) float smem_dyn[];
    float* s_lw = smem_dyn;                 // LL*CC floats
    float* s_d  = smem_dyn + LL * CC;       // 4 * 8 * SDS floats
    __shared__ double s_acc[4];
    const unsigned FULL = 0xffffffffu;

    int bid = blockIdx.x, t = threadIdx.x;
    int g = bid / NPART, part = bid - g * NPART;
    int wid = t >> 5, lane = t & 31;
    int c = lane >> 2, sub = lane & 3;      // Phase A roles
    int q = lane >> 3, ll = lane & 7;       // Phase B roles

    for (int i = t; i < LL * CC; i += 128) s_lw[i] = g_lw[g * (LL * CC) + i];
    __syncthreads();

    int s0 = g_off[g], e0 = g_off[g + 1];
    int tot = e0 - s0;
    int seg = (tot + NPART - 1) / NPART;
    int mystart = s0 + part * seg;
    int myend = mystart + seg; if (myend > e0) myend = e0;

    float* sd = s_d + wid * (8 * SDS);
    double acc = 0.0;

    for (int base = mystart + wid * 8; base < myend; base += 32) {
        int nc = myend - base; if (nc > 8) nc = 8;

        // ---- Phase A ----
        int myk = base + c;
        int4 cd = make_int4(0, 0, 0, 0);
        if (myk < myend) cd = __ldg(&g_cut[myk]);

        {
            const float4* cp = (const float4*)(clustering + (size_t)cd.z * LL);
            float4 c0 = __ldg(cp + 0), c1 = __ldg(cp + 1), c2 = __ldg(cp + 2), c3 = __ldg(cp + 3);
            unsigned long long cpk[16];
            cpk[0]  = pk(c0.x, c0.x); cpk[1]  = pk(c0.y, c0.y); cpk[2]  = pk(c0.z, c0.z); cpk[3]  = pk(c0.w, c0.w);
            cpk[4]  = pk(c1.x, c1.x); cpk[5]  = pk(c1.y, c1.y); cpk[6]  = pk(c1.z, c1.z); cpk[7]  = pk(c1.w, c1.w);
            cpk[8]  = pk(c2.x, c2.x); cpk[9]  = pk(c2.y, c2.y); cpk[10] = pk(c2.z, c2.z); cpk[11] = pk(c2.w, c2.w);
            cpk[12] = pk(c3.x, c3.x); cpk[13] = pk(c3.y, c3.y); cpk[14] = pk(c3.z, c3.z); cpk[15] = pk(c3.w, c3.w);

            const ulonglong2* lwv = (const ulonglong2*)s_lw;
            for (int chk = 0; chk < 14; chk++) {
                int i4 = sub * 14 + chk;
                unsigned long long a01 = 0ull, a23 = 0ull;
#pragma unroll
                for (int l = 0; l < 16; l++) {
                    ulonglong2 v = lwv[l * 56 + i4];
                    fma2(a01, cpk[l], v.x);
                    fma2(a23, cpk[l], v.y);
                }
                *(ulonglong2*)&sd[c * SDS + pos4(i4)] = make_ulonglong2(a01, a23);
            }
        }
        __syncwarp();

        // ---- Phase B: 2 passes of 4 quarter-cuts ----
        for (int p = 0; p < 2; p++) {
            int cc = (p << 2) + q;
            bool live = cc < nc;
            float x = __shfl_sync(FULL, __int_as_float(cd.x), cc << 2);
            int gl   = __shfl_sync(FULL, cd.y, cc << 2);
            const float4* splg = g_spl + (size_t)gl * CC;
            const float* dd = sd + cc * SDS;
            float lad = 0.f;

            // ===== step 1: 128 heights, lane owns i = 16*ll + j =====
            {
                const float* dp = dd + ll * 20;
                float4 da = *(const float4*)(dp);
                float4 db = *(const float4*)(dp + 4);
                float4 dc2 = *(const float4*)(dp + 8);
                float4 de = *(const float4*)(dp + 12);
                float dreg[16] = {da.x, da.y, da.z, da.w, db.x, db.y, db.z, db.w,
                                  dc2.x, dc2.y, dc2.z, dc2.w, de.x, de.y, de.z, de.w};
                float h[16], w[16];
                float area = 0.f; int cnt = 0;
#pragma unroll
                for (int j = 0; j < 16; j++) {
                    float4 pj = __ldg(splg + (j << 3) + ll);
                    float hv = __expf(pj.x + dreg[j]);
                    h[j] = hv; w[j] = pj.w;
                    cnt += (x >= pj.z) ? 1 : 0;
                    area = fmaf(hv, pj.y, area);
                }
                cnt += __shfl_xor_sync(FULL, cnt, 1, 8);
                cnt += __shfl_xor_sync(FULL, cnt, 2, 8);
                cnt += __shfl_xor_sync(FULL, cnt, 4, 8);
                int bin = iminmax(cnt - 1, 126);
                float wprev = __shfl_up_sync(FULL, w[15], 1, 8);
                float cdf = 0.f;
                int ib = ll << 4;
                float wim1 = wprev;
#pragma unroll
                for (int j = 0; j < 16; j++) {
                    int i = ib + j;
                    float ct = ((i < bin) ? 0.5f * w[j] : 0.f) + ((i >= 1 && i <= bin) ? 0.5f * wim1 : 0.f);
                    cdf = fmaf(h[j], ct, cdf);
                    wim1 = w[j];
                }
                area += __shfl_xor_sync(FULL, area, 4, 8);
                cdf  += __shfl_xor_sync(FULL, cdf, 4, 8);
                float v = (lane & 4) ? cdf : area;
                v += __shfl_xor_sync(FULL, v, 1, 8);
                v += __shfl_xor_sync(FULL, v, 2, 8);
                float o = __shfl_xor_sync(FULL, v, 4, 8);
                area = (lane & 4) ? o : v;
                cdf  = (lane & 4) ? v : o;

                int b1 = bin + 1;
                float4 spb  = __ldg(splg + ((bin & 15) << 3) + (bin >> 4));
                float4 spb1 = __ldg(splg + ((b1 & 15) << 3) + (b1 >> 4));
                float hl = __expf(spb.x + dd[posd1(bin)]);
                float hr = __expf(spb1.x + dd[posd1(b1)]);
                float inv = __fdividef(1.f, area);
                float alpha = __fdividef(x - spb.z, spb.w);
                float hln = hl * inv, hrn = hr * inv;
                x = (0.5f * (hrn - hln) * alpha + hln) * spb.w * alpha + cdf * inv;
                lad += __logf(fmaf(hrn - hln, alpha, hln));
            }

            // ===== step 2: 64 heights, lane owns i = 8*ll + j =====
            {
                const float* dp = dd + 160 + ll * 12;
                float4 da = *(const float4*)(dp);
                float4 db = *(const float4*)(dp + 4);
                float dreg[8] = {da.x, da.y, da.z, da.w, db.x, db.y, db.z, db.w};
                float h[8], w[8];
                float area = 0.f; int cnt = 0;
#pragma unroll
                for (int j = 0; j < 8; j++) {
                    float4 pj = __ldg(splg + 128 + (j << 3) + ll);
                    float hv = __expf(pj.x + dreg[j]);
                    h[j] = hv; w[j] = pj.w;
                    cnt += (x >= pj.z) ? 1 : 0;
                    area = fmaf(hv, pj.y, area);
                }
                cnt += __shfl_xor_sync(FULL, cnt, 1, 8);
                cnt += __shfl_xor_sync(FULL, cnt, 2, 8);
                cnt += __shfl_xor_sync(FULL, cnt, 4, 8);
                int bin = iminmax(cnt - 1, 62);
                float wprev = __shfl_up_sync(FULL, w[7], 1, 8);
                float cdf = 0.f;
                int ib = ll << 3;
                float wim1 = wprev;
#pragma unroll
                for (int j = 0; j < 8; j++) {
                    int i = ib + j;
                    float ct = ((i < bin) ? 0.5f * w[j] : 0.f) + ((i >= 1 && i <= bin) ? 0.5f * wim1 : 0.f);
                    cdf = fmaf(h[j], ct, cdf);
                    wim1 = w[j];
                }
                area += __shfl_xor_sync(FULL, area, 4, 8);
                cdf  += __shfl_xor_sync(FULL, cdf, 4, 8);
                float v = (lane & 4) ? cdf : area;
                v += __shfl_xor_sync(FULL, v, 1, 8);
                v += __shfl_xor_sync(FULL, v, 2, 8);
                float o = __shfl_xor_sync(FULL, v, 4, 8);
                area = (lane & 4) ? o : v;
                cdf  = (lane & 4) ? v : o;

                int b1 = bin + 1;
                float4 spb  = __ldg(splg + 128 + ((bin & 7) << 3) + (bin >> 3));
                float4 spb1 = __ldg(splg + 128 + ((b1 & 7) << 3) + (b1 >> 3));
                float hl = __expf(spb.x + dd[posd2(bin)]);
                float hr = __expf(spb1.x + dd[posd2(b1)]);
                float inv = __fdividef(1.f, area);
                float alpha = __fdividef(x - spb.z, spb.w);
                float hln = hl * inv, hrn = hr * inv;
                x = (0.5f * (hrn - hln) * alpha + hln) * spb.w * alpha + cdf * inv;
                lad += __logf(fmaf(hrn - hln, alpha, hln));
            }

            // ===== step 3: 32 heights, lane owns i = 4*ll + j =====
            {
                const float* dp = dd + 256 + (ll << 2);
                float4 da = *(const float4*)(dp);
                float dreg[4] = {da.x, da.y, da.z, da.w};
                float h[4], w[4];
                float area = 0.f; int cnt = 0;
#pragma unroll
                for (int j = 0; j < 4; j++) {
                    float4 pj = __ldg(splg + 192 + (j << 3) + ll);
                    float hv = __expf(pj.x + dreg[j]);
                    h[j] = hv; w[j] = pj.w;
                    cnt += (x >= pj.z) ? 1 : 0;
                    area = fmaf(hv, pj.y, area);
                }
                cnt += __shfl_xor_sync(FULL, cnt, 1, 8);
                cnt += __shfl_xor_sync(FULL, cnt, 2, 8);
                cnt += __shfl_xor_sync(FULL, cnt, 4, 8);
                int bin = iminmax(cnt - 1, 30);
                float wprev = __shfl_up_sync(FULL, w[3], 1, 8);
                float cdf = 0.f;
                int ib = ll << 2;
                float wim1 = wprev;
#pragma unroll
                for (int j = 0; j < 4; j++) {
                    int i = ib + j;
                    float ct = ((i < bin) ? 0.5f * w[j] : 0.f) + ((i >= 1 && i <= bin) ? 0.5f * wim1 : 0.f);
                    cdf = fmaf(h[j], ct, cdf);
                    wim1 = w[j];
                }
                area += __shfl_xor_sync(FULL, area, 4, 8);
                cdf  += __shfl_xor_sync(FULL, cdf, 4, 8);
                float v = (lane & 4) ? cdf : area;
                v += __shfl_xor_sync(FULL, v, 1, 8);
                v += __shfl_xor_sync(FULL, v, 2, 8);
                float o = __shfl_xor_sync(FULL, v, 4, 8);
                area = (lane & 4) ? o : v;
                cdf  = (lane & 4) ? v : o;

                int b1 = bin + 1;
                float4 spb  = __ldg(splg + 192 + ((bin & 3) << 3) + (bin >> 2));
                float4 spb1 = __ldg(splg + 192 + ((b1 & 3) << 3) + (b1 >> 2));
                float hl = __expf(spb.x + dd[posd3(bin)]);
                float hr = __expf(spb1.x + dd[posd3(b1)]);
                float inv = __fdividef(1.f, area);
                float alpha = __fdividef(x - spb.z, spb.w);
                float hln = hl * inv, hrn = hr * inv;
                x = (0.5f * (hrn - hln) * alpha + hln) * spb.w * alpha + cdf * inv;
                lad += __logf(fmaf(hrn - hln, alpha, hln));
            }

            if (live && ll == 0) acc += (double)lad;
        }
        __syncwarp();
    }

    // reduce quarter accumulators (lanes 0,8,16,24 hold values; others are 0)
    acc += __shfl_xor_sync(FULL, acc, 8);
    acc += __shfl_xor_sync(FULL, acc, 16);
    if (lane == 0) s_acc[wid] = acc;
    __syncthreads();
    if (t == 0) {
        double tt = s_acc[0] + s_acc[1] + s_acc[2] + s_acc[3];
        atomicAdd(&g_acc[0], tt);
    }
}

// ---------------- K5: z ----------------
__global__ void k_z(const float* __restrict__ clustering,
                    const float* __restrict__ rho_weight,
                    const float* __restrict__ rho_bias, int GT) {
    int j = blockIdx.x * blockDim.x + threadIdx.x;
    if (j >= GT) return;
    int b0 = blockIdx.y * 8;
    float lb = __logf(rho_bias[j]);
    const float4* rw = (const float4*)(rho_weight + (size_t)j * LL);
    float4 r0 = rw[0], r1 = rw[1], r2 = rw[2], r3 = rw[3];
#pragma unroll
    for (int bi = 0; bi < 8; bi++) {
        int b = b0 + bi;
        const float4* cp = (const float4*)(clustering + (size_t)b * LL);
        float4 c0 = cp[0], c1 = cp[1], c2 = cp[2], c3 = cp[3];
        float z = lb;
        z = fmaf(c0.x, r0.x, z); z = fmaf(c0.y, r0.y, z); z = fmaf(c0.z, r0.z, z); z = fmaf(c0.w, r0.w, z);
        z = fmaf(c1.x, r1.x, z); z = fmaf(c1.y, r1.y, z); z = fmaf(c1.z, r1.z, z); z = fmaf(c1.w, r1.w, z);
        z = fmaf(c2.x, r2.x, z); z = fmaf(c2.y, r2.y, z); z = fmaf(c2.z, r2.z, z); z = fmaf(c2.w, r2.w, z);
        z = fmaf(c3.x, r3.x, z); z = fmaf(c3.y, r3.y, z); z = fmaf(c3.z, r3.z, z); z = fmaf(c3.w, r3.w, z);
        g_z[(size_t)b * GT + j] = z;
    }
}

// ---------------- K6: logsumexp ----------------
__global__ void k_lse(int GT) {
    int b = blockIdx.x, t = threadIdx.x;
    const float* zr = g_z + (size_t)b * GT;
    float m = -1e30f, s = 0.f;
    for (int j = t; j < GT; j += blockDim.x) {
        float v = zr[j];
        if (v > m) { s = s * __expf(m - v) + 1.f; m = v; }
        else       { s += __expf(v - m); }
    }
    __shared__ float sm[256], ss[256];
    sm[t] = m; ss[t] = s; __syncthreads();
    for (int o = 128; o; o >>= 1) {
        if (t < o) {
            float m1 = sm[t], s1 = ss[t], m2 = sm[t + o], s2 = ss[t + o];
            float M = fmaxf(m1, m2);
            sm[t] = M;
            ss[t] = s1 * __expf(m1 - M) + s2 * __expf(m2 - M);
        }
        __syncthreads();
    }
    if (t == 0) g_logZ[b] = sm[0] + logf(ss[0]);
}

// ---------------- K7: rho gather-sum ----------------
__global__ void k_rho(const int* __restrict__ lcgi, int n, int GT) {
    int i = blockIdx.x * blockDim.x + threadIdx.x;
    float v = 0.f;
    if (i < n) {
        int li = lcgi[i];
        v = __ldg(&g_z[li]) - __ldg(&g_logZ[li / GT]);
    }
    __shared__ double sd_[256];
    sd_[threadIdx.x] = (double)v;
    __syncthreads();
    for (int o = 128; o; o >>= 1) {
        if (threadIdx.x < o) sd_[threadIdx.x] += sd_[threadIdx.x + o];
        __syncthreads();
    }
    if (threadIdx.x == 0) atomicAdd(&g_acc[0], sd_[0]);
}

// ---------------- K8: finalize + restore ----------------
__global__ void k_final(float* out, int G, int N, float logGT) {
    int t = threadIdx.x;
    if (t == 0) {
        double cnt = (double)G * (double)(LL * CC + LL);
        out[0] = (float)(-g_acc[0] - (double)N * (double)logGT
                         - g_acc[1] + 0.5 * LOG2PI * cnt);
    }
    __syncthreads();
    for (int i = t; i <= G; i += blockDim.x) g_off[i] = 0;
    if (t < 2) g_acc[t] = 0.0;
}

// ---------------- launch ----------------
extern "C" void kernel_launch(void* const* d_in, const int* in_sizes, int n_in,
                              void* d_out, int out_size) {
    const float* clustering    = (const float*)d_in[0];
    const float* coordinates   = (const float*)d_in[1];
    const int*   genes_oi      = (const int*)d_in[2];
    const int*   local_gene_ix = (const int*)d_in[3];
    const int*   lci           = (const int*)d_in[4];
    const int*   lcgi          = (const int*)d_in[5];
    const float* logit_weight  = (const float*)d_in[6];
    const float* rho_weight    = (const float*)d_in[7];
    const float* rho_bias      = (const float*)d_in[8];
    const float* uh            = (const float*)d_in[9];
    const float* uw            = (const float*)d_in[10];

    int N  = in_sizes[1];
    int G  = in_sizes[2];
    int B  = in_sizes[0] / LL;
    int GT = in_sizes[8];

    cudaFuncSetAttribute(k_main, cudaFuncAttributeMaxDynamicSharedMemorySize, KMAIN_SMEM);

    int histBlocks = (N + 127) / 128;
    k_pergene_hist<<<G + histBlocks, 128>>>(genes_oi, logit_weight, rho_weight,
                                            uh, uw, lci, N, G);
    k_scan<<<1, 512>>>(G);
    k_scatter<<<(N + 255) / 256, 256>>>(lci, local_gene_ix, lcgi, coordinates, N, G);
    k_main<<<NPART * G, 128, KMAIN_SMEM>>>(clustering, G);
    k_z<<<dim3((GT + 255) / 256, B / 8), 256>>>(clustering, rho_weight, rho_bias, GT);
    k_lse<<<B, 256>>>(GT);
    k_rho<<<(N + 255) / 256, 256>>>(lcgi, N, GT);
    k_final<<<1, 512>>>((float*)d_out, G, N, logf((float)GT));
}